// round 16
// baseline (speedup 1.0000x reference)
#include <cuda_runtime.h>

// Packed-f32x2 fused kernel: 4 samples/thread processed as 2 packed pairs.
// All heavy math (dots, tanh Newton, Taylor sincos, rotations, z) runs on
// Blackwell f32x2 packed-FMA; MUFU = 4 ex2/sample only; post-MLP scalar.
//
// Math (verified R2-R6):
//   h_j  = tanh(W1[j,:].x + b1[j]);  th_j = h_j + qw[0,j]
//   z    = K1*cos(th1)cos(th2)cos(th3) - K2*sin(th0)sin(th1)
//   out  = relu(z*W2 + b2) @ W3^T + b3
// tanh: u = 2log2e*(dot+b); e = ex2(-|u|); tanh = copysign((1-e)*recip(1+e), u)
// sin/cos(th) from Taylor sincos(h), |h|<1, rotated by precomputed cos/sin(qw0).

typedef unsigned long long u64;

__device__ __forceinline__ u64 pack2(float lo, float hi) {
    u64 r; asm("mov.b64 %0, {%1, %2};" : "=l"(r) : "f"(lo), "f"(hi)); return r;
}
__device__ __forceinline__ void unpack2(u64 v, float& lo, float& hi) {
    asm("mov.b64 {%0, %1}, %2;" : "=f"(lo), "=f"(hi) : "l"(v));
}
__device__ __forceinline__ u64 fma2(u64 a, u64 b, u64 c) {
    u64 r; asm("fma.rn.f32x2 %0, %1, %2, %3;" : "=l"(r) : "l"(a), "l"(b), "l"(c)); return r;
}
__device__ __forceinline__ u64 mul2(u64 a, u64 b) {
    u64 r; asm("mul.rn.f32x2 %0, %1, %2;" : "=l"(r) : "l"(a), "l"(b)); return r;
}
__device__ __forceinline__ u64 add2(u64 a, u64 b) {
    u64 r; asm("add.rn.f32x2 %0, %1, %2;" : "=l"(r) : "l"(a), "l"(b)); return r;
}

__global__ void __launch_bounds__(256, 2) qnn_fused(
    const float4* __restrict__ x4, float2* __restrict__ out, int stride,
    const float* __restrict__ W1, const float* __restrict__ b1,
    const float* __restrict__ qw, const float* __restrict__ W2,
    const float* __restrict__ b2, const float* __restrict__ W3,
    const float* __restrict__ b3)
{
    // spk: duplicated (packed) constants. [0:16) W1s, [16:20) b1s,
    // [20:24) cos(qw0), [24:28) sin(qw0), [28:32) -sin(qw0), [32] K1, [33] -K2.
    __shared__ u64 spk[34];
    // ss: scalar post-MLP consts: [0:4) W2, [4:8) b2, [8:16) W3, [16:18) b3.
    __shared__ float ss[18];

    const int i = blockIdx.x * blockDim.x + threadIdx.x;

    // ---- hoisted sample loads (before the barrier) ----
    float4 xv0 = x4[i];
    float4 xv1 = x4[i + stride];
    float4 xv2 = x4[i + 2 * stride];
    float4 xv3 = x4[i + 3 * stride];

    {
        const float SC = 2.8853900817779268f;    // +2*log2(e)
        int t = threadIdx.x;
        if (t < 16)      { float v = SC * W1[t];        spk[t] = pack2(v, v); }
        else if (t < 20) { float v = SC * b1[t - 16];   spk[t] = pack2(v, v); }
        else if (t < 24) { float v = __cosf(qw[t - 20]); spk[t] = pack2(v, v); }
        else if (t < 28) { float v = __sinf(qw[t - 24]); spk[t] = pack2(v, v); }
        else if (t < 32) { float v = -__sinf(qw[t - 28]); spk[t] = pack2(v, v); }
        else if (t == 32) { float v = __cosf(qw[8]);     spk[32] = pack2(v, v); }
        else if (t == 33) {
            float v = -(__sinf(qw[8]) * __cosf(qw[4]) * __cosf(qw[5]));
            spk[33] = pack2(v, v);
        }
        else if (t < 38) ss[t - 34] = W2[t - 34];
        else if (t < 42) ss[t - 38 + 4] = b2[t - 38];
        else if (t < 50) ss[t - 42 + 8] = W3[t - 42];
        else if (t < 52) ss[t - 50 + 16] = b3[t - 50];
    }
    __syncthreads();

    const u64 SIGN  = 0x8000000080000000ull;
    const u64 ONE2  = 0x3F8000003F800000ull;   // {1.0f, 1.0f}
    const u64 TWO2  = 0x4000000040000000ull;   // {2.0f, 2.0f}
    const u64 NONE2 = 0xBF800000BF800000ull;   // {-1.0f, -1.0f}
    const u64 SEEDA = pack2(-0.47058823529411764f, -0.47058823529411764f);
    const u64 SEEDB = pack2(1.4117647058823530f,  1.4117647058823530f);
    const u64 C3 = pack2(-1.6666667e-1f, -1.6666667e-1f);
    const u64 C5 = pack2( 8.3333333e-3f,  8.3333333e-3f);
    const u64 C7 = pack2(-1.9841270e-4f, -1.9841270e-4f);
    const u64 DH = pack2(-0.5f, -0.5f);
    const u64 D4 = pack2( 4.1666667e-2f,  4.1666667e-2f);
    const u64 D6 = pack2(-1.3888889e-3f, -1.3888889e-3f);

    const float W20 = ss[0], W21 = ss[1], W22 = ss[2], W23 = ss[3];
    const float B20 = ss[4], B21 = ss[5], B22 = ss[6], B23 = ss[7];
    const float W3a0 = ss[8], W3a1 = ss[9], W3a2 = ss[10], W3a3 = ss[11];
    const float W3b0 = ss[12], W3b1 = ss[13], W3b2 = ss[14], W3b3 = ss[15];
    const float B30 = ss[16], B31 = ss[17];

    float4 xa_[2] = {xv0, xv2};
    float4 xb_[2] = {xv1, xv3};

    #pragma unroll
    for (int p = 0; p < 2; ++p) {
        float4 xa = xa_[p], xb = xb_[p];
        u64 X0 = pack2(xa.x, xb.x);
        u64 X1 = pack2(xa.y, xb.y);
        u64 X2 = pack2(xa.z, xb.z);
        u64 X3 = pack2(xa.w, xb.w);

        u64 SN[4], CS[4];
        #pragma unroll
        for (int j = 0; j < 4; ++j) {
            u64 U = fma2(spk[4*j+0], X0, fma2(spk[4*j+1], X1,
                    fma2(spk[4*j+2], X2, fma2(spk[4*j+3], X3, spk[16+j]))));
            u64 A = U | SIGN;                    // -|u| per half
            float al, ah; unpack2(A, al, ah);
            float el, eh;
            asm("ex2.approx.f32 %0, %1;" : "=f"(el) : "f"(al));
            asm("ex2.approx.f32 %0, %1;" : "=f"(eh) : "f"(ah));
            u64 E = pack2(el, eh);               // e in (0,1]
            u64 D = add2(E, ONE2);               // d in [1,2]
            u64 ND = D ^ SIGN;                   // -d
            u64 W = fma2(SEEDA, D, SEEDB);       // seed, |err|<=1/17
            W = mul2(W, fma2(ND, W, TWO2));
            W = mul2(W, fma2(ND, W, TWO2));      // recip(d), err ~1.2e-5
            u64 NUM = fma2(E, NONE2, ONE2);      // 1 - e
            u64 T = mul2(NUM, W);                // tanh(|u|) >= 0
            u64 H = T | (U & SIGN);              // copysign -> h in (-1,1)
            u64 T2 = mul2(H, H);
            SN[j] = mul2(H, fma2(T2, fma2(T2, fma2(T2, C7, C5), C3), ONE2));
            CS[j] = fma2(T2, fma2(T2, fma2(T2, D6, D4), DH), ONE2);
        }

        // rotate by qw0: s = sn*cq + cs*sq ; c = cs*cq - sn*sq
        u64 s0 = fma2(SN[0], spk[20], mul2(CS[0], spk[24]));
        u64 s1 = fma2(SN[1], spk[21], mul2(CS[1], spk[25]));
        u64 c1 = fma2(SN[1], spk[29], mul2(CS[1], spk[21]));
        u64 c2 = fma2(SN[2], spk[30], mul2(CS[2], spk[22]));
        u64 c3 = fma2(SN[3], spk[31], mul2(CS[3], spk[23]));

        u64 Z = fma2(spk[32], mul2(c1, mul2(c2, c3)), mul2(spk[33], mul2(s0, s1)));
        float za, zb; unpack2(Z, za, zb);

        // scalar post-MLP per sample
        {
            float h20 = fmaxf(fmaf(za, W20, B20), 0.f);
            float h21 = fmaxf(fmaf(za, W21, B21), 0.f);
            float h22 = fmaxf(fmaf(za, W22, B22), 0.f);
            float h23 = fmaxf(fmaf(za, W23, B23), 0.f);
            float o0 = fmaf(h20, W3a0, fmaf(h21, W3a1, fmaf(h22, W3a2, fmaf(h23, W3a3, B30))));
            float o1 = fmaf(h20, W3b0, fmaf(h21, W3b1, fmaf(h22, W3b2, fmaf(h23, W3b3, B31))));
            out[i + (2 * p) * stride] = make_float2(o0, o1);
        }
        {
            float h20 = fmaxf(fmaf(zb, W20, B20), 0.f);
            float h21 = fmaxf(fmaf(zb, W21, B21), 0.f);
            float h22 = fmaxf(fmaf(zb, W22, B22), 0.f);
            float h23 = fmaxf(fmaf(zb, W23, B23), 0.f);
            float o0 = fmaf(h20, W3a0, fmaf(h21, W3a1, fmaf(h22, W3a2, fmaf(h23, W3a3, B30))));
            float o1 = fmaf(h20, W3b0, fmaf(h21, W3b1, fmaf(h22, W3b2, fmaf(h23, W3b3, B31))));
            out[i + (2 * p + 1) * stride] = make_float2(o0, o1);
        }
    }
}

extern "C" void kernel_launch(void* const* d_in, const int* in_sizes, int n_in,
                              void* d_out, int out_size) {
    const float* x  = (const float*)d_in[0];
    const float* W1 = (const float*)d_in[1];
    const float* b1 = (const float*)d_in[2];
    const float* qw = (const float*)d_in[3];
    const float* W2 = (const float*)d_in[4];
    const float* b2 = (const float*)d_in[5];
    const float* W3 = (const float*)d_in[6];
    const float* b3 = (const float*)d_in[7];

    int n = in_sizes[0] / 4;    // samples (1048576)
    int stride = n / 4;         // 4 samples per thread
    const int threads = 256;
    const int blocks = stride / threads;   // 1024
    qnn_fused<<<blocks, threads>>>((const float4*)x, (float2*)d_out, stride,
                                   W1, b1, qw, W2, b2, W3, b3);
}

// round 17
// speedup vs baseline: 1.0229x; 1.0229x over previous
#include <cuda_runtime.h>

// R6 math (FMA-heavy, 4 MUFU/sample) in the fused shell (parallel smem
// prelude, hoisted loads). 4 samples/thread, phase-strided, grid 1024.
//
// Math (verified R2-R6):
//   h_j  = tanh(W1[j,:].x + b1[j]);  th_j = h_j + qw[0,j]
//   z    = K1*cos(th1)cos(th2)cos(th3) - K2*sin(th0)sin(th1)
//          K1 = cos(qw[2,0]),  K2 = sin(qw[2,0])*cos(qw[1,0])*cos(qw[1,1])
//   out  = relu(z*W2 + b2) @ W3^T + b3
//
// tanh: e = ex2(-2log2e*|u|), d=1+e in [1,2], FMA-Newton recip (2 steps),
//       t = copysign((1-e)*r, u).   sincos of h in (-1,1): FMA Taylor.
//   sin/cos(th) = rotation of (sin h, cos h) by precomputed (cos q, sin q).

__device__ __forceinline__ float fast_tanh(float x) {
    float ax = fabsf(x);
    float e;
    asm("ex2.approx.f32 %0, %1;" : "=f"(e) : "f"(-2.8853900817779268f * ax));
    float d = 1.0f + e;                                   // [1,2]
    float r = fmaf(-0.47058823529411764f, d, 1.4117647058823530f);
    r = r * fmaf(-d, r, 2.0f);
    r = r * fmaf(-d, r, 2.0f);                            // err ~1.2e-5
    return copysignf((1.0f - e) * r, x);
}

__device__ __forceinline__ void sincos_t(float h, float& sn, float& cs) {
    float t2 = h * h;
    sn = h * fmaf(t2, fmaf(t2, fmaf(t2, -1.9841270e-4f, 8.3333333e-3f), -1.6666667e-1f), 1.0f);
    cs = fmaf(t2, fmaf(t2, fmaf(t2, -1.3888889e-3f, 4.1666667e-2f), -0.5f), 1.0f);
}

__global__ void __launch_bounds__(256) qnn_fused(
    const float4* __restrict__ x4, float2* __restrict__ out, int stride,
    const float* __restrict__ W1, const float* __restrict__ b1,
    const float* __restrict__ qw, const float* __restrict__ W2,
    const float* __restrict__ b2, const float* __restrict__ W3,
    const float* __restrict__ b3)
{
    // sc layout (float4): [0..3] W1 rows, [4] b1, [5] cos(qw0), [6] sin(qw0),
    // [7] (K1, K2, b3_0, b3_1), [8] W2, [9] b2, [10] W3 row0, [11] W3 row1
    __shared__ float4 sc[12];

    const int i = blockIdx.x * blockDim.x + threadIdx.x;

    // ---- hoisted sample loads (before the barrier) ----
    float4 xv0 = x4[i];
    float4 xv1 = x4[i + stride];
    float4 xv2 = x4[i + 2 * stride];
    float4 xv3 = x4[i + 3 * stride];

    {
        float* v = reinterpret_cast<float*>(sc);
        int t = threadIdx.x;
        if (t < 16)      v[t] = W1[t];                      // W1 rows 0..3
        else if (t < 20) v[t] = b1[t - 16];                 // b1
        else if (t < 24) v[t] = __cosf(qw[t - 20]);         // cos(qw0_i)
        else if (t < 28) v[t] = __sinf(qw[t - 24]);         // sin(qw0_i)
        else if (t == 28) v[28] = __cosf(qw[8]);            // K1
        else if (t == 29) v[29] = __sinf(qw[8]) * __cosf(qw[4]) * __cosf(qw[5]); // K2
        else if (t < 32) v[t] = b3[t - 30];                 // b3
        else if (t < 36) v[t] = W2[t - 32];                 // W2
        else if (t < 40) v[t] = b2[t - 36];                 // b2
        else if (t < 48) v[t] = W3[t - 40];                 // W3 (2x4)
    }
    __syncthreads();

    const float4 r0 = sc[0], r1 = sc[1], r2 = sc[2], r3 = sc[3], bb = sc[4];
    const float4 cq = sc[5], sq = sc[6], kk = sc[7];
    const float4 W2v = sc[8], b2v = sc[9], W3a = sc[10], W3b = sc[11];

    float4 xv[4] = {xv0, xv1, xv2, xv3};

    #pragma unroll
    for (int k = 0; k < 4; ++k) {
        float4 x = xv[k];

        float h0 = fast_tanh(fmaf(r0.x, x.x, fmaf(r0.y, x.y, fmaf(r0.z, x.z, fmaf(r0.w, x.w, bb.x)))));
        float h1 = fast_tanh(fmaf(r1.x, x.x, fmaf(r1.y, x.y, fmaf(r1.z, x.z, fmaf(r1.w, x.w, bb.y)))));
        float h2 = fast_tanh(fmaf(r2.x, x.x, fmaf(r2.y, x.y, fmaf(r2.z, x.z, fmaf(r2.w, x.w, bb.z)))));
        float h3 = fast_tanh(fmaf(r3.x, x.x, fmaf(r3.y, x.y, fmaf(r3.z, x.z, fmaf(r3.w, x.w, bb.w)))));

        float sn, cs;
        sincos_t(h0, sn, cs);
        float sth0 = fmaf(sn, cq.x,  cs * sq.x);

        sincos_t(h1, sn, cs);
        float cth1 = fmaf(cs, cq.y, -sn * sq.y);
        float sth1 = fmaf(sn, cq.y,  cs * sq.y);

        sincos_t(h2, sn, cs);
        float cth2 = fmaf(cs, cq.z, -sn * sq.z);

        sincos_t(h3, sn, cs);
        float cth3 = fmaf(cs, cq.w, -sn * sq.w);

        float z = fmaf(kk.x, cth1 * cth2 * cth3, -kk.y * (sth0 * sth1));

        float h20 = fmaxf(fmaf(z, W2v.x, b2v.x), 0.f);
        float h21 = fmaxf(fmaf(z, W2v.y, b2v.y), 0.f);
        float h22 = fmaxf(fmaf(z, W2v.z, b2v.z), 0.f);
        float h23 = fmaxf(fmaf(z, W2v.w, b2v.w), 0.f);
        float o0 = fmaf(h20, W3a.x, fmaf(h21, W3a.y, fmaf(h22, W3a.z, fmaf(h23, W3a.w, kk.z))));
        float o1 = fmaf(h20, W3b.x, fmaf(h21, W3b.y, fmaf(h22, W3b.z, fmaf(h23, W3b.w, kk.w))));
        out[i + k * stride] = make_float2(o0, o1);
    }
}

extern "C" void kernel_launch(void* const* d_in, const int* in_sizes, int n_in,
                              void* d_out, int out_size) {
    const float* x  = (const float*)d_in[0];
    const float* W1 = (const float*)d_in[1];
    const float* b1 = (const float*)d_in[2];
    const float* qw = (const float*)d_in[3];
    const float* W2 = (const float*)d_in[4];
    const float* b2 = (const float*)d_in[5];
    const float* W3 = (const float*)d_in[6];
    const float* b3 = (const float*)d_in[7];

    int n = in_sizes[0] / 4;    // samples (1048576)
    int stride = n / 4;         // 4 samples per thread
    const int threads = 256;
    const int blocks = stride / threads;   // 1024
    qnn_fused<<<blocks, threads>>>((const float4*)x, (float2*)d_out, stride,
                                   W1, b1, qw, W2, b2, W3, b3);
}